// round 15
// baseline (speedup 1.0000x reference)
#include <cuda_runtime.h>
#include <cuda_fp16.h>
#include <math.h>
#include <stdint.h>

// Problem constants
#define BATCH   2
#define S_LEN   2048
#define DMODEL  1024
#define NHEAD   16
#define HDIM    64
#define QKVD    (3*DMODEL)     // 3072
#define ROWS    (BATCH*S_LEN)  // 4096
#define BH      (BATCH*NHEAD)  // 32

// Scratch (device globals). fp16 stored as ushort.
__device__ unsigned short g_xh[ROWS * DMODEL];             // LN output
__device__ unsigned short g_wqh[QKVD * DMODEL];            // weights
__device__ unsigned short g_wph[DMODEL * DMODEL];
__device__ unsigned short g_ch[ROWS * DMODEL];             // ctx
__device__ unsigned short g_qhh[BH * S_LEN * HDIM];        // Q (post-rope, *0.125*log2e)
__device__ unsigned short g_khh[BH * S_LEN * HDIM];        // K (post-rope)
__device__ unsigned short g_vseq[ROWS * DMODEL];           // V seq-major fp16
__device__ unsigned short g_vth[BH * HDIM * S_LEN];        // V^T
__device__ float2 g_rtab[S_LEN * 32];                      // rope (cos,sin) table

// ---------------------------------------------------------------------------
// helpers
// ---------------------------------------------------------------------------
__device__ __forceinline__ uint32_t f2h2(float a, float b) {
    __half2 t = __floats2half2_rn(a, b);
    return *reinterpret_cast<uint32_t*>(&t);
}
__device__ __forceinline__ uint32_t ex2_h2(uint32_t x) {
    uint32_t r;
    asm("ex2.approx.f16x2 %0, %1;" : "=r"(r) : "r"(x));
    return r;
}
__device__ __forceinline__ uint32_t sptr(const void* p) {
    return (uint32_t)__cvta_generic_to_shared(p);
}
__device__ __forceinline__ void cp16(void* dst, const void* src) {
    asm volatile("cp.async.cg.shared.global [%0], [%1], 16;\n"
                 :: "r"(sptr(dst)), "l"(src));
}
__device__ __forceinline__ void cp_commit() { asm volatile("cp.async.commit_group;\n"); }
__device__ __forceinline__ void cp_wait0()  { asm volatile("cp.async.wait_group 0;\n"); }
__device__ __forceinline__ void cp_wait1()  { asm volatile("cp.async.wait_group 1;\n"); }

__device__ __forceinline__ void ldsm4(uint32_t* r, const void* p) {
    asm volatile("ldmatrix.sync.aligned.m8n8.x4.shared.b16 {%0,%1,%2,%3}, [%4];\n"
                 : "=r"(r[0]), "=r"(r[1]), "=r"(r[2]), "=r"(r[3]) : "r"(sptr(p)));
}
// f16 inputs, f32 accumulate
__device__ __forceinline__ void mma_f16(float* c, const uint32_t* a, const uint32_t* b) {
    asm volatile(
        "mma.sync.aligned.m16n8k16.row.col.f32.f16.f16.f32 "
        "{%0,%1,%2,%3}, {%4,%5,%6,%7}, {%8,%9}, {%0,%1,%2,%3};\n"
        : "+f"(c[0]), "+f"(c[1]), "+f"(c[2]), "+f"(c[3])
        : "r"(a[0]), "r"(a[1]), "r"(a[2]), "r"(a[3]), "r"(b[0]), "r"(b[1]));
}

// ---------------------------------------------------------------------------
// 0) RoPE table: (cos, sin) of s * 10000^(-2i/64), double precision.
// ---------------------------------------------------------------------------
__global__ void __launch_bounds__(256) rope_table_kernel(float2* __restrict__ tab)
{
    int idx = blockIdx.x * 256 + threadIdx.x;   // s*32 + i
    int i = idx & 31, s = idx >> 5;
    const double C = 0.28782844202394213;       // ln(10000)/32
    double ang = (double)s * exp(-C * (double)i);
    double n   = rint(ang * 0.15915494309189535);
    double ar  = ang - n * 6.283185307179586;
    tab[idx] = make_float2((float)cos(ar), (float)sin(ar));
}

// ---------------------------------------------------------------------------
// 1) LayerNorm -> fp16 output
// ---------------------------------------------------------------------------
__global__ void __launch_bounds__(256) ln_split_kernel(
    const float* __restrict__ x, const float* __restrict__ gamma,
    const float* __restrict__ beta, unsigned short* __restrict__ yh)
{
    __shared__ float red_s[8], red_ss[8];
    __shared__ float sh_mean, sh_inv;
    int row = blockIdx.x;
    int tid = threadIdx.x;
    const float4* xr = (const float4*)(x + (size_t)row * DMODEL);
    float4 v = xr[tid];
    float s  = v.x + v.y + v.z + v.w;
    float ss = v.x*v.x + v.y*v.y + v.z*v.z + v.w*v.w;
    #pragma unroll
    for (int off = 16; off > 0; off >>= 1) {
        s  += __shfl_down_sync(0xffffffffu, s,  off);
        ss += __shfl_down_sync(0xffffffffu, ss, off);
    }
    int wid = tid >> 5, lane = tid & 31;
    if (lane == 0) { red_s[wid] = s; red_ss[wid] = ss; }
    __syncthreads();
    if (tid == 0) {
        float S = 0.f, SS = 0.f;
        #pragma unroll
        for (int i = 0; i < 8; ++i) { S += red_s[i]; SS += red_ss[i]; }
        float mean = S * (1.f / DMODEL);
        float var  = SS * (1.f / DMODEL) - mean * mean;
        sh_mean = mean;
        sh_inv  = rsqrtf(var + 1e-5f);
    }
    __syncthreads();
    float mean = sh_mean, inv = sh_inv;
    float4 gv = ((const float4*)gamma)[tid];
    float4 bv = ((const float4*)beta)[tid];
    float o0 = (v.x - mean) * inv * gv.x + bv.x;
    float o1 = (v.y - mean) * inv * gv.y + bv.y;
    float o2 = (v.z - mean) * inv * gv.z + bv.z;
    float o3 = (v.w - mean) * inv * gv.w + bv.w;
    uint2 hv = make_uint2(f2h2(o0, o1), f2h2(o2, o3));
    *(uint2*)(yh + (size_t)row * DMODEL + tid * 4) = hv;
}

// ---------------------------------------------------------------------------
// weights: fp32 -> fp16, 4 elements/thread
// ---------------------------------------------------------------------------
__global__ void __launch_bounds__(256) w_f16_kernel(
    const float* __restrict__ x, unsigned short* __restrict__ hi, int n4)
{
    int i = blockIdx.x * 256 + threadIdx.x;
    if (i >= n4) return;
    float4 v = ((const float4*)x)[i];
    uint2 hv = make_uint2(f2h2(v.x, v.y), f2h2(v.z, v.w));
    *(uint2*)(hi + (size_t)i * 4) = hv;
}

// ---------------------------------------------------------------------------
// 2a) QKV GEMM with fused bias + RoPE(table) + head-major fp16 output.
//     Block 128x128, BK=32, 4 warps (2x2), warp tile 64x64.
// ---------------------------------------------------------------------------
#define GPAD 40
#define GTILE (128 * GPAD)            // ushorts per tile
#define GSTAGE (2 * GTILE)            // Ah,Bh
#define GEMM_SMEM (2 * GSTAGE * 2)    // bytes = 40960

__global__ void __launch_bounds__(128) qkv_gemm_rope(
    const unsigned short* __restrict__ Ahg, const unsigned short* __restrict__ Bhg,
    const float* __restrict__ bias, const float2* __restrict__ rtab,
    unsigned short* __restrict__ Qh, unsigned short* __restrict__ Kh,
    unsigned short* __restrict__ Vseq)
{
    extern __shared__ unsigned short smg[];
    const int K = DMODEL;
    int t = threadIdx.x;
    int wid = t >> 5, lane = t & 31;
    int wm = wid >> 1, wn = wid & 1;
    int g = lane >> 2, q = lane & 3;
    int mb = blockIdx.y * 128, nb = blockIdx.x * 128;

    float acc[4][8][4];
    #pragma unroll
    for (int mt = 0; mt < 4; ++mt)
        #pragma unroll
        for (int nt = 0; nt < 8; ++nt)
            #pragma unroll
            for (int e = 0; e < 4; ++e) acc[mt][nt][e] = 0.f;

    const int NKB = K >> 5;

    auto load_stage = [&](int st, int k0) {
        unsigned short* base = smg + st * GSTAGE;
        #pragma unroll
        for (int i = 0; i < 4; ++i) {
            int ch = t + i * 128;
            int row = ch >> 2, c = ch & 3;
            int soff = row * GPAD + c * 8;
            size_t goffA = (size_t)(mb + row) * K + k0 + c * 8;
            size_t goffB = (size_t)(nb + row) * K + k0 + c * 8;
            cp16(base + soff,         Ahg + goffA);
            cp16(base + GTILE + soff, Bhg + goffB);
        }
        cp_commit();
    };

    load_stage(0, 0);

    for (int kb = 0; kb < NKB; ++kb) {
        cp_wait0();
        __syncthreads();
        if (kb + 1 < NKB) load_stage((kb + 1) & 1, (kb + 1) << 5);

        unsigned short* base = smg + (kb & 1) * GSTAGE;
        unsigned short* sAh = base;
        unsigned short* sBh = base + GTILE;

        #pragma unroll
        for (int kk = 0; kk < 2; ++kk) {
            uint32_t ah[4][4];
            #pragma unroll
            for (int mt = 0; mt < 4; ++mt) {
                int r = wm * 64 + mt * 16 + (lane & 15);
                int c = kk * 16 + (lane >> 4) * 8;
                ldsm4(ah[mt], sAh + r * GPAD + c);
            }
            uint32_t bh2[8][2];
            #pragma unroll
            for (int p = 0; p < 4; ++p) {
                int r = wn * 64 + p * 16 + ((lane >> 4) & 1) * 8 + (lane & 7);
                int c = kk * 16 + ((lane >> 3) & 1) * 8;
                uint32_t tmp[4];
                ldsm4(tmp, sBh + r * GPAD + c);
                bh2[2*p][0] = tmp[0]; bh2[2*p][1] = tmp[1];
                bh2[2*p+1][0] = tmp[2]; bh2[2*p+1][1] = tmp[3];
            }
            #pragma unroll
            for (int mt = 0; mt < 4; ++mt)
                #pragma unroll
                for (int nt = 0; nt < 8; ++nt)
                    mma_f16(acc[mt][nt], ah[mt], bh2[nt]);
        }
    }

    // ---- fused epilogue: bias + rope(table) + head-major fp16 stores ----
    int gid  = (nb + wn * 64) >> 6;      // 0..47
    int head = gid / 3;
    int part = gid - head * 3;           // 0=q, 1=k, 2=v
    const float* bgrp = bias + (gid << 6);
    const float QS = 0.125f * 1.4426950408889634f;

    if (part < 2) {
        float scale = (part == 0) ? QS : 1.f;
        unsigned short* dstbuf = (part == 0) ? Qh : Kh;
        #pragma unroll
        for (int mt = 0; mt < 4; ++mt) {
            #pragma unroll
            for (int half = 0; half < 2; ++half) {
                int sb = mb + wm * 64 + mt * 16 + g + half * 8;
                int srow = sb & (S_LEN - 1);
                int bb = sb >> 11;
                const float2* trow = rtab + srow * 32;
                size_t dbase = ((size_t)(bb * NHEAD + head) * S_LEN + srow) * HDIM;
                int e0 = half * 2, e1 = half * 2 + 1;
                #pragma unroll
                for (int nt = 0; nt < 4; ++nt) {
                    int i0 = nt * 8 + 2 * q;     // < 32, even
                    float4 cs = *(const float4*)(trow + i0);  // (c0,s0,c1,s1)
                    float x1a = acc[mt][nt][e0]     + bgrp[i0];
                    float x1b = acc[mt][nt][e1]     + bgrp[i0 + 1];
                    float x2a = acc[mt][nt + 4][e0] + bgrp[i0 + 32];
                    float x2b = acc[mt][nt + 4][e1] + bgrp[i0 + 33];
                    float o1a = (x1a * cs.x - x2a * cs.y) * scale;
                    float o1b = (x1b * cs.z - x2b * cs.w) * scale;
                    float o2a = (x2a * cs.x + x1a * cs.y) * scale;
                    float o2b = (x2b * cs.z + x1b * cs.w) * scale;
                    *(uint32_t*)(dstbuf + dbase + i0)      = f2h2(o1a, o1b);
                    *(uint32_t*)(dstbuf + dbase + i0 + 32) = f2h2(o2a, o2b);
                }
            }
        }
    } else {
        #pragma unroll
        for (int mt = 0; mt < 4; ++mt) {
            #pragma unroll
            for (int half = 0; half < 2; ++half) {
                int sb = mb + wm * 64 + mt * 16 + g + half * 8;
                size_t dbase = (size_t)sb * DMODEL + head * HDIM;
                int e0 = half * 2, e1 = half * 2 + 1;
                #pragma unroll
                for (int nt = 0; nt < 8; ++nt) {
                    int d0 = nt * 8 + 2 * q;
                    float va = acc[mt][nt][e0] + bgrp[d0];
                    float vb = acc[mt][nt][e1] + bgrp[d0 + 1];
                    *(uint32_t*)(Vseq + dbase + d0) = f2h2(va, vb);
                }
            }
        }
    }
}

// ---------------------------------------------------------------------------
// 2b) Generic pure-fp16 GEMM (fp32 out + bias) for the projection.
// ---------------------------------------------------------------------------
__global__ void __launch_bounds__(128) mma_gemm_smem(
    const unsigned short* __restrict__ Ahg, const unsigned short* __restrict__ Bhg,
    const float* __restrict__ bias, float* __restrict__ C,
    int M, int N, int K)
{
    extern __shared__ unsigned short smg[];
    int t = threadIdx.x;
    int wid = t >> 5, lane = t & 31;
    int wm = wid >> 1, wn = wid & 1;
    int g = lane >> 2, q = lane & 3;
    int mb = blockIdx.y * 128, nb = blockIdx.x * 128;

    float acc[4][8][4];
    #pragma unroll
    for (int mt = 0; mt < 4; ++mt)
        #pragma unroll
        for (int nt = 0; nt < 8; ++nt)
            #pragma unroll
            for (int e = 0; e < 4; ++e) acc[mt][nt][e] = 0.f;

    const int NKB = K >> 5;

    auto load_stage = [&](int st, int k0) {
        unsigned short* base = smg + st * GSTAGE;
        #pragma unroll
        for (int i = 0; i < 4; ++i) {
            int ch = t + i * 128;
            int row = ch >> 2, c = ch & 3;
            int soff = row * GPAD + c * 8;
            size_t goffA = (size_t)(mb + row) * K + k0 + c * 8;
            size_t goffB = (size_t)(nb + row) * K + k0 + c * 8;
            cp16(base + soff,         Ahg + goffA);
            cp16(base + GTILE + soff, Bhg + goffB);
        }
        cp_commit();
    };

    load_stage(0, 0);

    for (int kb = 0; kb < NKB; ++kb) {
        cp_wait0();
        __syncthreads();
        if (kb + 1 < NKB) load_stage((kb + 1) & 1, (kb + 1) << 5);

        unsigned short* base = smg + (kb & 1) * GSTAGE;
        unsigned short* sAh = base;
        unsigned short* sBh = base + GTILE;

        #pragma unroll
        for (int kk = 0; kk < 2; ++kk) {
            uint32_t ah[4][4];
            #pragma unroll
            for (int mt = 0; mt < 4; ++mt) {
                int r = wm * 64 + mt * 16 + (lane & 15);
                int c = kk * 16 + (lane >> 4) * 8;
                ldsm4(ah[mt], sAh + r * GPAD + c);
            }
            uint32_t bh2[8][2];
            #pragma unroll
            for (int p = 0; p < 4; ++p) {
                int r = wn * 64 + p * 16 + ((lane >> 4) & 1) * 8 + (lane & 7);
                int c = kk * 16 + ((lane >> 3) & 1) * 8;
                uint32_t tmp[4];
                ldsm4(tmp, sBh + r * GPAD + c);
                bh2[2*p][0] = tmp[0]; bh2[2*p][1] = tmp[1];
                bh2[2*p+1][0] = tmp[2]; bh2[2*p+1][1] = tmp[3];
            }
            #pragma unroll
            for (int mt = 0; mt < 4; ++mt)
                #pragma unroll
                for (int nt = 0; nt < 8; ++nt)
                    mma_f16(acc[mt][nt], ah[mt], bh2[nt]);
        }
    }

    #pragma unroll
    for (int mt = 0; mt < 4; ++mt) {
        #pragma unroll
        for (int nt = 0; nt < 8; ++nt) {
            int r = mb + wm * 64 + mt * 16 + g;
            int c = nb + wn * 64 + nt * 8 + q * 2;
            float b0 = bias[c], b1 = bias[c + 1];
            float2 v0; v0.x = acc[mt][nt][0] + b0; v0.y = acc[mt][nt][1] + b1;
            float2 v1; v1.x = acc[mt][nt][2] + b0; v1.y = acc[mt][nt][3] + b1;
            *(float2*)(C + (size_t)r * N + c)       = v0;
            *(float2*)(C + (size_t)(r + 8) * N + c) = v1;
        }
    }
}

// ---------------------------------------------------------------------------
// 3) V transpose (fp16 in, fp16 out): Vt[bh][d][s].
// ---------------------------------------------------------------------------
__global__ void __launch_bounds__(256) v_transpose_kernel(
    const unsigned short* __restrict__ vseq, unsigned short* __restrict__ Vth)
{
    __shared__ unsigned short tile[64][66];
    int st = blockIdx.x, bh = blockIdx.y;
    int b = bh >> 4, h = bh & 15;
    int t = threadIdx.x;
    #pragma unroll
    for (int it = 0; it < 4; ++it) {
        int id = t + it * 256;            // 0..1023
        int sl = id >> 4, f4 = id & 15;
        size_t src = (size_t)(b * S_LEN + st * 64 + sl) * DMODEL + h * HDIM + f4 * 4;
        uint2 v = *(const uint2*)(vseq + src);
        *(uint32_t*)&tile[sl][f4 * 4]     = v.x;
        *(uint32_t*)&tile[sl][f4 * 4 + 2] = v.y;
    }
    __syncthreads();
    #pragma unroll
    for (int it = 0; it < 16; ++it) {
        int d  = it * 4 + (t >> 6);
        int sl = t & 63;
        size_t dst = ((size_t)bh * HDIM + d) * S_LEN + st * 64 + sl;
        Vth[dst] = tile[sl][d];
    }
}

// ---------------------------------------------------------------------------
// 4) fp16 flash attention, KV tile 128, f16x2 exp2, l-via-MMA ones rows,
//    pipelined S(t+1)-before-PV(t).
// ---------------------------------------------------------------------------
#define APAD 72            // K/Q row pad
#define VPAD 136           // V^T row pad
#define VROWS 80           // 64 d-rows + ones rows 64..71 + zero 72..79
#define AQT (128 * APAD)
#define KT  (128 * APAD)
#define VT  (VROWS * VPAD)
#define AST (KT + VT)
#define ATT_SMEM ((AQT + 2 * AST) * 2)

__global__ void __launch_bounds__(256) attn_mma_kernel(
    const unsigned short* __restrict__ Qh,
    const unsigned short* __restrict__ Kh, const unsigned short* __restrict__ Vth,
    unsigned short* __restrict__ Ch)
{
    extern __shared__ unsigned short sma[];
    unsigned short* sQh = sma;
    unsigned short* sKV = sma + AQT;

    int qt = gridDim.x - 1 - blockIdx.x;
    int bh = blockIdx.y;
    int b = bh >> 4, h = bh & 15;
    int t = threadIdx.x;
    int w = t >> 5, lane = t & 31;
    int g = lane >> 2, q = lane & 3;

    auto load_kv = [&](int st, int kt) {
        unsigned short* sg = sKV + st * AST;
        size_t kbase = ((size_t)bh * S_LEN + kt * 128) * HDIM;
        #pragma unroll
        for (int i = 0; i < 4; ++i) {
            int ch = t + i * 256;
            int row = ch >> 3, c = ch & 7;
            cp16(sg + row * APAD + c * 8, Kh + kbase + row * 64 + c * 8);
        }
        #pragma unroll
        for (int i = 0; i < 4; ++i) {
            int ch = t + i * 256;
            int row = ch >> 4, c = ch & 15;
            size_t vsrc = ((size_t)bh * HDIM + row) * S_LEN + kt * 128 + c * 8;
            cp16(sg + KT + row * VPAD + c * 8, Vth + vsrc);
        }
        cp_commit();
    };

    int nk = qt + 1;

    // prologue: Q, kv0, (kv1)
    size_t qbase = ((size_t)bh * S_LEN + qt * 128) * HDIM;
    #pragma unroll
    for (int i = 0; i < 4; ++i) {
        int ch = t + i * 256;
        int row = ch >> 3, c = ch & 7;
        cp16(sQh + row * APAD + c * 8, Qh + qbase + row * 64 + c * 8);
    }
    cp_commit();
    load_kv(0, 0);
    if (nk > 1) load_kv(1, 1);

    // init V^T rows 64..79 in both stages (cp.async never touches them)
    for (int idx = t; idx < 16 * VPAD; idx += 256) {
        int row = idx / VPAD, col = idx % VPAD;
        unsigned short val = (row < 8 && col < 128) ? (unsigned short)0x3C00
                                                    : (unsigned short)0;
        sKV[KT + (64 + row) * VPAD + col]       = val;
        sKV[AST + KT + (64 + row) * VPAD + col] = val;
    }

    if (nk > 1) cp_wait1(); else cp_wait0();
    __syncthreads();

    uint32_t qfh[4][4];
    #pragma unroll
    for (int kk = 0; kk < 4; ++kk) {
        int r = w * 16 + (lane & 15);
        int c = kk * 16 + (lane >> 4) * 8;
        ldsm4(qfh[kk], sQh + r * APAD + c);
    }

    float o[9][4];
    #pragma unroll
    for (int nt = 0; nt < 9; ++nt)
        #pragma unroll
        for (int e = 0; e < 4; ++e) o[nt][e] = 0.f;
    float mA = -1e30f, mB = -1e30f;

    int qrA = qt * 128 + w * 16 + g;
    float s_acc[16][4];
    uint32_t pA[16], pB[16];

    auto s_phase = [&](int st) {
        unsigned short* sK_ = sKV + st * AST;
        #pragma unroll
        for (int nt = 0; nt < 16; ++nt)
            #pragma unroll
            for (int e = 0; e < 4; ++e) s_acc[nt][e] = 0.f;
        #pragma unroll
        for (int kk = 0; kk < 4; ++kk) {
            uint32_t bh2[16][2];
            #pragma unroll
            for (int p = 0; p < 8; ++p) {
                int r = p * 16 + ((lane >> 4) & 1) * 8 + (lane & 7);
                int c = kk * 16 + ((lane >> 3) & 1) * 8;
                uint32_t tmp[4];
                ldsm4(tmp, sK_ + r * APAD + c);
                bh2[2*p][0] = tmp[0]; bh2[2*p][1] = tmp[1];
                bh2[2*p+1][0] = tmp[2]; bh2[2*p+1][1] = tmp[3];
            }
            #pragma unroll
            for (int nt = 0; nt < 16; ++nt)
                mma_f16(s_acc[nt], qfh[kk], bh2[nt]);
        }
    };

    auto pv_phase = [&](int st) {
        unsigned short* sV_ = sKV + st * AST + KT;
        #pragma unroll
        for (int kk = 0; kk < 8; ++kk) {
            int n0 = 2 * kk, n1 = 2 * kk + 1;
            uint32_t ph[4];
            ph[0] = pA[n0]; ph[1] = pB[n0];
            ph[2] = pA[n1]; ph[3] = pB[n1];
            uint32_t vh2[10][2];
            #pragma unroll
            for (int p = 0; p < 5; ++p) {
                int r = p * 16 + ((lane >> 4) & 1) * 8 + (lane & 7);
                int c = kk * 16 + ((lane >> 3) & 1) * 8;
                uint32_t tmp[4];
                ldsm4(tmp, sV_ + r * VPAD + c);
                vh2[2*p][0] = tmp[0]; vh2[2*p][1] = tmp[1];
                vh2[2*p+1][0] = tmp[2]; vh2[2*p+1][1] = tmp[3];
            }
            #pragma unroll
            for (int nt = 0; nt < 9; ++nt)
                mma_f16(o[nt], ph, vh2[nt]);
        }
    };

    s_phase(0);

    for (int kt = 0; kt < nk; ++kt) {
        // ---- softmax on tile kt ----
        int kb0 = kt * 128;
        if (kb0 + 127 > qrA) {
            #pragma unroll
            for (int nt = 0; nt < 16; ++nt) {
                int colb = kb0 + nt * 8 + 2 * q;
                if (colb     > qrA)     s_acc[nt][0] = -1e30f;
                if (colb + 1 > qrA)     s_acc[nt][1] = -1e30f;
                if (colb     > qrA + 8) s_acc[nt][2] = -1e30f;
                if (colb + 1 > qrA + 8) s_acc[nt][3] = -1e30f;
            }
        }
        float mxA = -1e30f, mxB = -1e30f;
        #pragma unroll
        for (int nt = 0; nt < 16; ++nt) {
            mxA = fmaxf(mxA, fmaxf(s_acc[nt][0], s_acc[nt][1]));
            mxB = fmaxf(mxB, fmaxf(s_acc[nt][2], s_acc[nt][3]));
        }
        mxA = fmaxf(mxA, __shfl_xor_sync(0xffffffffu, mxA, 1));
        mxA = fmaxf(mxA, __shfl_xor_sync(0xffffffffu, mxA, 2));
        mxB = fmaxf(mxB, __shfl_xor_sync(0xffffffffu, mxB, 1));
        mxB = fmaxf(mxB, __shfl_xor_sync(0xffffffffu, mxB, 2));
        float mnA = fmaxf(mA, mxA), mnB = fmaxf(mB, mxB);
        float corrA = exp2f(mA - mnA), corrB = exp2f(mB - mnB);
        mA = mnA;  mB = mnB;
        #pragma unroll
        for (int nt = 0; nt < 16; ++nt) {
            pA[nt] = ex2_h2(f2h2(s_acc[nt][0] - mnA, s_acc[nt][1] - mnA));
            pB[nt] = ex2_h2(f2h2(s_acc[nt][2] - mnB, s_acc[nt][3] - mnB));
        }
        #pragma unroll
        for (int nt = 0; nt < 9; ++nt) {
            o[nt][0] *= corrA; o[nt][1] *= corrA;
            o[nt][2] *= corrB; o[nt][3] *= corrB;
        }

        // ---- S(kt+1) before PV(kt) ----
        if (kt + 1 < nk) {
            cp_wait0();
            __syncthreads();
            s_phase((kt + 1) & 1);
        }

        pv_phase(kt & 1);

        __syncthreads();
        if (kt + 2 < nk) load_kv(kt & 1, kt + 2);
    }

    float invA = 1.f / o[8][0], invB = 1.f / o[8][2];
    int rowA = qt * 128 + w * 16 + g;
    size_t baseA = ((size_t)(b * S_LEN + rowA)) * DMODEL + h * HDIM;
    size_t baseB = baseA + (size_t)8 * DMODEL;
    #pragma unroll
    for (int nt = 0; nt < 8; ++nt) {
        int c = nt * 8 + 2 * q;
        float a0 = o[nt][0] * invA, a1 = o[nt][1] * invA;
        float b0 = o[nt][2] * invB, b1 = o[nt][3] * invB;
        *(uint32_t*)(Ch + baseA + c) = f2h2(a0, a1);
        *(uint32_t*)(Ch + baseB + c) = f2h2(b0, b1);
    }
}

// ---------------------------------------------------------------------------
// Launcher
// ---------------------------------------------------------------------------
extern "C" void kernel_launch(void* const* d_in, const int* in_sizes, int n_in,
                              void* d_out, int out_size)
{
    const float* hs     = (const float*)d_in[0];
    const float* gamma  = (const float*)d_in[1];
    const float* beta   = (const float*)d_in[2];
    const float* qkv_w  = (const float*)d_in[3];
    const float* qkv_b  = (const float*)d_in[4];
    const float* proj_w = (const float*)d_in[5];
    const float* proj_b = (const float*)d_in[6];
    float* out = (float*)d_out;

    void *pxh, *pwqh, *pwph, *pch, *pqh, *pkh, *pvs, *pvh, *prt;
    cudaGetSymbolAddress(&pxh,  g_xh);
    cudaGetSymbolAddress(&pwqh, g_wqh); cudaGetSymbolAddress(&pwph, g_wph);
    cudaGetSymbolAddress(&pch,  g_ch);
    cudaGetSymbolAddress(&pqh,  g_qhh); cudaGetSymbolAddress(&pkh,  g_khh);
    cudaGetSymbolAddress(&pvs,  g_vseq); cudaGetSymbolAddress(&pvh,  g_vth);
    cudaGetSymbolAddress(&prt,  g_rtab);

    cudaFuncSetAttribute(qkv_gemm_rope,
        cudaFuncAttributeMaxDynamicSharedMemorySize, GEMM_SMEM);
    cudaFuncSetAttribute(mma_gemm_smem,
        cudaFuncAttributeMaxDynamicSharedMemorySize, GEMM_SMEM);
    cudaFuncSetAttribute(attn_mma_kernel,
        cudaFuncAttributeMaxDynamicSharedMemorySize, ATT_SMEM);

    // 0) RoPE table
    rope_table_kernel<<<(S_LEN*32)/256, 256>>>((float2*)prt);

    // 1) LayerNorm -> fp16
    ln_split_kernel<<<ROWS, 256>>>(hs, gamma, beta, (unsigned short*)pxh);

    // weight conversions
    w_f16_kernel<<<(QKVD*DMODEL/4)/256, 256>>>(qkv_w,
        (unsigned short*)pwqh, QKVD*DMODEL/4);
    w_f16_kernel<<<(DMODEL*DMODEL/4)/256, 256>>>(proj_w,
        (unsigned short*)pwph, DMODEL*DMODEL/4);

    // 2) QKV GEMM with fused bias+rope(table)+relayout (fp16 out)
    qkv_gemm_rope<<<dim3(QKVD/128, ROWS/128), 128, GEMM_SMEM>>>(
        (unsigned short*)pxh, (unsigned short*)pwqh, qkv_b, (const float2*)prt,
        (unsigned short*)pqh, (unsigned short*)pkh, (unsigned short*)pvs);

    // 3) V transpose (fp16 -> fp16)
    v_transpose_kernel<<<dim3(S_LEN/64, BH), 256>>>(
        (unsigned short*)pvs, (unsigned short*)pvh);

    // 4) Attention (pipelined S/PV overlap)
    attn_mma_kernel<<<dim3(S_LEN/128, BH), 256, ATT_SMEM>>>(
        (unsigned short*)pqh, (unsigned short*)pkh, (unsigned short*)pvh,
        (unsigned short*)pch);

    // 5) Output projection (fp32 out)
    mma_gemm_smem<<<dim3(DMODEL/128, ROWS/128), 128, GEMM_SMEM>>>(
        (unsigned short*)pch, (unsigned short*)pwph,
        proj_b, out, ROWS, DMODEL, DMODEL);
}

// round 16
// speedup vs baseline: 1.0415x; 1.0415x over previous
#include <cuda_runtime.h>
#include <cuda_fp16.h>
#include <math.h>
#include <stdint.h>

// Problem constants
#define BATCH   2
#define S_LEN   2048
#define DMODEL  1024
#define NHEAD   16
#define HDIM    64
#define QKVD    (3*DMODEL)     // 3072
#define ROWS    (BATCH*S_LEN)  // 4096
#define BH      (BATCH*NHEAD)  // 32

// Scratch (device globals). fp16 stored as ushort.
__device__ unsigned short g_xh[ROWS * DMODEL];             // LN output
__device__ unsigned short g_wqh[QKVD * DMODEL];            // weights
__device__ unsigned short g_wph[DMODEL * DMODEL];
__device__ unsigned short g_ch[ROWS * DMODEL];             // ctx
__device__ unsigned short g_qhh[BH * S_LEN * HDIM];        // Q (post-rope, *0.125*log2e)
__device__ unsigned short g_khh[BH * S_LEN * HDIM];        // K (post-rope)
__device__ unsigned short g_vseq[ROWS * DMODEL];           // V seq-major fp16
__device__ unsigned short g_vth[BH * HDIM * S_LEN];        // V^T

// ---------------------------------------------------------------------------
// helpers
// ---------------------------------------------------------------------------
__device__ __forceinline__ uint32_t f2h2(float a, float b) {
    __half2 t = __floats2half2_rn(a, b);
    return *reinterpret_cast<uint32_t*>(&t);
}
__device__ __forceinline__ uint32_t ex2_h2(uint32_t x) {
    uint32_t r;
    asm("ex2.approx.f16x2 %0, %1;" : "=r"(r) : "r"(x));
    return r;
}
__device__ __forceinline__ uint32_t sptr(const void* p) {
    return (uint32_t)__cvta_generic_to_shared(p);
}
__device__ __forceinline__ void cp16(void* dst, const void* src) {
    asm volatile("cp.async.cg.shared.global [%0], [%1], 16;\n"
                 :: "r"(sptr(dst)), "l"(src));
}
__device__ __forceinline__ void cp_commit() { asm volatile("cp.async.commit_group;\n"); }
__device__ __forceinline__ void cp_wait0()  { asm volatile("cp.async.wait_group 0;\n"); }
__device__ __forceinline__ void cp_wait1()  { asm volatile("cp.async.wait_group 1;\n"); }

__device__ __forceinline__ void ldsm4(uint32_t* r, const void* p) {
    asm volatile("ldmatrix.sync.aligned.m8n8.x4.shared.b16 {%0,%1,%2,%3}, [%4];\n"
                 : "=r"(r[0]), "=r"(r[1]), "=r"(r[2]), "=r"(r[3]) : "r"(sptr(p)));
}
// f16 inputs, f32 accumulate
__device__ __forceinline__ void mma_f16(float* c, const uint32_t* a, const uint32_t* b) {
    asm volatile(
        "mma.sync.aligned.m16n8k16.row.col.f32.f16.f16.f32 "
        "{%0,%1,%2,%3}, {%4,%5,%6,%7}, {%8,%9}, {%0,%1,%2,%3};\n"
        : "+f"(c[0]), "+f"(c[1]), "+f"(c[2]), "+f"(c[3])
        : "r"(a[0]), "r"(a[1]), "r"(a[2]), "r"(a[3]), "r"(b[0]), "r"(b[1]));
}

// rope cos/sin from precomputed inverse-frequency (Cody-Waite float reduction)
__device__ __forceinline__ void rope_cs_f(float s, float invf, float& c, float& sn) {
    float ang = s * invf;
    float n = rintf(ang * 0.15915494309189535f);
    float ar = fmaf(n, -6.28125f, ang);
    ar = fmaf(n, -1.9353071795864769e-3f, ar);
    c  = __cosf(ar);
    sn = __sinf(ar);
}

// ---------------------------------------------------------------------------
// 1) LayerNorm -> fp16 output
// ---------------------------------------------------------------------------
__global__ void __launch_bounds__(256) ln_split_kernel(
    const float* __restrict__ x, const float* __restrict__ gamma,
    const float* __restrict__ beta, unsigned short* __restrict__ yh)
{
    __shared__ float red_s[8], red_ss[8];
    __shared__ float sh_mean, sh_inv;
    int row = blockIdx.x;
    int tid = threadIdx.x;
    const float4* xr = (const float4*)(x + (size_t)row * DMODEL);
    float4 v = xr[tid];
    float s  = v.x + v.y + v.z + v.w;
    float ss = v.x*v.x + v.y*v.y + v.z*v.z + v.w*v.w;
    #pragma unroll
    for (int off = 16; off > 0; off >>= 1) {
        s  += __shfl_down_sync(0xffffffffu, s,  off);
        ss += __shfl_down_sync(0xffffffffu, ss, off);
    }
    int wid = tid >> 5, lane = tid & 31;
    if (lane == 0) { red_s[wid] = s; red_ss[wid] = ss; }
    __syncthreads();
    if (tid == 0) {
        float S = 0.f, SS = 0.f;
        #pragma unroll
        for (int i = 0; i < 8; ++i) { S += red_s[i]; SS += red_ss[i]; }
        float mean = S * (1.f / DMODEL);
        float var  = SS * (1.f / DMODEL) - mean * mean;
        sh_mean = mean;
        sh_inv  = rsqrtf(var + 1e-5f);
    }
    __syncthreads();
    float mean = sh_mean, inv = sh_inv;
    float4 gv = ((const float4*)gamma)[tid];
    float4 bv = ((const float4*)beta)[tid];
    float o0 = (v.x - mean) * inv * gv.x + bv.x;
    float o1 = (v.y - mean) * inv * gv.y + bv.y;
    float o2 = (v.z - mean) * inv * gv.z + bv.z;
    float o3 = (v.w - mean) * inv * gv.w + bv.w;
    uint2 hv = make_uint2(f2h2(o0, o1), f2h2(o2, o3));
    *(uint2*)(yh + (size_t)row * DMODEL + tid * 4) = hv;
}

// ---------------------------------------------------------------------------
// weights: fp32 -> fp16, 4 elements/thread
// ---------------------------------------------------------------------------
__global__ void __launch_bounds__(256) w_f16_kernel(
    const float* __restrict__ x, unsigned short* __restrict__ hi, int n4)
{
    int i = blockIdx.x * 256 + threadIdx.x;
    if (i >= n4) return;
    float4 v = ((const float4*)x)[i];
    uint2 hv = make_uint2(f2h2(v.x, v.y), f2h2(v.z, v.w));
    *(uint2*)(hi + (size_t)i * 4) = hv;
}

// ---------------------------------------------------------------------------
// 2a) QKV GEMM with fused bias + RoPE + head-major fp16 output.
//     Block 128x128, BK=32, 4 warps (2x2), warp tile 64x64.
//     invf (exp2) hoisted: 8 MUFU once instead of 64 recomputes.
// ---------------------------------------------------------------------------
#define GPAD 40
#define GTILE (128 * GPAD)            // ushorts per tile
#define GSTAGE (2 * GTILE)            // Ah,Bh
#define GEMM_SMEM (2 * GSTAGE * 2)    // bytes = 40960

__global__ void __launch_bounds__(128) qkv_gemm_rope(
    const unsigned short* __restrict__ Ahg, const unsigned short* __restrict__ Bhg,
    const float* __restrict__ bias,
    unsigned short* __restrict__ Qh, unsigned short* __restrict__ Kh,
    unsigned short* __restrict__ Vseq)
{
    extern __shared__ unsigned short smg[];
    const int K = DMODEL;
    int t = threadIdx.x;
    int wid = t >> 5, lane = t & 31;
    int wm = wid >> 1, wn = wid & 1;
    int g = lane >> 2, q = lane & 3;
    int mb = blockIdx.y * 128, nb = blockIdx.x * 128;

    float acc[4][8][4];
    #pragma unroll
    for (int mt = 0; mt < 4; ++mt)
        #pragma unroll
        for (int nt = 0; nt < 8; ++nt)
            #pragma unroll
            for (int e = 0; e < 4; ++e) acc[mt][nt][e] = 0.f;

    const int NKB = K >> 5;

    auto load_stage = [&](int st, int k0) {
        unsigned short* base = smg + st * GSTAGE;
        #pragma unroll
        for (int i = 0; i < 4; ++i) {
            int ch = t + i * 128;
            int row = ch >> 2, c = ch & 3;
            int soff = row * GPAD + c * 8;
            size_t goffA = (size_t)(mb + row) * K + k0 + c * 8;
            size_t goffB = (size_t)(nb + row) * K + k0 + c * 8;
            cp16(base + soff,         Ahg + goffA);
            cp16(base + GTILE + soff, Bhg + goffB);
        }
        cp_commit();
    };

    load_stage(0, 0);

    for (int kb = 0; kb < NKB; ++kb) {
        cp_wait0();
        __syncthreads();
        if (kb + 1 < NKB) load_stage((kb + 1) & 1, (kb + 1) << 5);

        unsigned short* base = smg + (kb & 1) * GSTAGE;
        unsigned short* sAh = base;
        unsigned short* sBh = base + GTILE;

        #pragma unroll
        for (int kk = 0; kk < 2; ++kk) {
            uint32_t ah[4][4];
            #pragma unroll
            for (int mt = 0; mt < 4; ++mt) {
                int r = wm * 64 + mt * 16 + (lane & 15);
                int c = kk * 16 + (lane >> 4) * 8;
                ldsm4(ah[mt], sAh + r * GPAD + c);
            }
            uint32_t bh2[8][2];
            #pragma unroll
            for (int p = 0; p < 4; ++p) {
                int r = wn * 64 + p * 16 + ((lane >> 4) & 1) * 8 + (lane & 7);
                int c = kk * 16 + ((lane >> 3) & 1) * 8;
                uint32_t tmp[4];
                ldsm4(tmp, sBh + r * GPAD + c);
                bh2[2*p][0] = tmp[0]; bh2[2*p][1] = tmp[1];
                bh2[2*p+1][0] = tmp[2]; bh2[2*p+1][1] = tmp[3];
            }
            #pragma unroll
            for (int mt = 0; mt < 4; ++mt)
                #pragma unroll
                for (int nt = 0; nt < 8; ++nt)
                    mma_f16(acc[mt][nt], ah[mt], bh2[nt]);
        }
    }

    // ---- fused epilogue: bias + rope + head-major fp16 stores ----
    int gid  = (nb + wn * 64) >> 6;      // 0..47
    int head = gid / 3;
    int part = gid - head * 3;           // 0=q, 1=k, 2=v
    const float* bgrp = bias + (gid << 6);
    const float QS = 0.125f * 1.4426950408889634f;

    if (part < 2) {
        float scale = (part == 0) ? QS : 1.f;
        unsigned short* dstbuf = (part == 0) ? Qh : Kh;
        // hoisted inverse frequencies: i0 = nt*8+2q, and i0+1
        float invf[4][2];
        #pragma unroll
        for (int nt = 0; nt < 4; ++nt) {
            int i0 = nt * 8 + 2 * q;
            invf[nt][0] = exp2f(-0.4152410118609203f * (float)i0);
            invf[nt][1] = exp2f(-0.4152410118609203f * (float)(i0 + 1));
        }
        #pragma unroll
        for (int mt = 0; mt < 4; ++mt) {
            #pragma unroll
            for (int half = 0; half < 2; ++half) {
                int sb = mb + wm * 64 + mt * 16 + g + half * 8;
                int srow = sb & (S_LEN - 1);
                int bb = sb >> 11;
                float sf = (float)srow;
                size_t dbase = ((size_t)(bb * NHEAD + head) * S_LEN + srow) * HDIM;
                int e0 = half * 2, e1 = half * 2 + 1;
                #pragma unroll
                for (int nt = 0; nt < 4; ++nt) {
                    int i0 = nt * 8 + 2 * q;     // < 32
                    float c0, s0, c1, s1;
                    rope_cs_f(sf, invf[nt][0], c0, s0);
                    rope_cs_f(sf, invf[nt][1], c1, s1);
                    float x1a = acc[mt][nt][e0]     + bgrp[i0];
                    float x1b = acc[mt][nt][e1]     + bgrp[i0 + 1];
                    float x2a = acc[mt][nt + 4][e0] + bgrp[i0 + 32];
                    float x2b = acc[mt][nt + 4][e1] + bgrp[i0 + 33];
                    float o1a = (x1a * c0 - x2a * s0) * scale;
                    float o1b = (x1b * c1 - x2b * s1) * scale;
                    float o2a = (x2a * c0 + x1a * s0) * scale;
                    float o2b = (x2b * c1 + x1b * s1) * scale;
                    *(uint32_t*)(dstbuf + dbase + i0)      = f2h2(o1a, o1b);
                    *(uint32_t*)(dstbuf + dbase + i0 + 32) = f2h2(o2a, o2b);
                }
            }
        }
    } else {
        #pragma unroll
        for (int mt = 0; mt < 4; ++mt) {
            #pragma unroll
            for (int half = 0; half < 2; ++half) {
                int sb = mb + wm * 64 + mt * 16 + g + half * 8;
                size_t dbase = (size_t)sb * DMODEL + head * HDIM;
                int e0 = half * 2, e1 = half * 2 + 1;
                #pragma unroll
                for (int nt = 0; nt < 8; ++nt) {
                    int d0 = nt * 8 + 2 * q;
                    float va = acc[mt][nt][e0] + bgrp[d0];
                    float vb = acc[mt][nt][e1] + bgrp[d0 + 1];
                    *(uint32_t*)(Vseq + dbase + d0) = f2h2(va, vb);
                }
            }
        }
    }
}

// ---------------------------------------------------------------------------
// 2b) Generic pure-fp16 GEMM (fp32 out + bias) for the projection.
// ---------------------------------------------------------------------------
__global__ void __launch_bounds__(128) mma_gemm_smem(
    const unsigned short* __restrict__ Ahg, const unsigned short* __restrict__ Bhg,
    const float* __restrict__ bias, float* __restrict__ C,
    int M, int N, int K)
{
    extern __shared__ unsigned short smg[];
    int t = threadIdx.x;
    int wid = t >> 5, lane = t & 31;
    int wm = wid >> 1, wn = wid & 1;
    int g = lane >> 2, q = lane & 3;
    int mb = blockIdx.y * 128, nb = blockIdx.x * 128;

    float acc[4][8][4];
    #pragma unroll
    for (int mt = 0; mt < 4; ++mt)
        #pragma unroll
        for (int nt = 0; nt < 8; ++nt)
            #pragma unroll
            for (int e = 0; e < 4; ++e) acc[mt][nt][e] = 0.f;

    const int NKB = K >> 5;

    auto load_stage = [&](int st, int k0) {
        unsigned short* base = smg + st * GSTAGE;
        #pragma unroll
        for (int i = 0; i < 4; ++i) {
            int ch = t + i * 128;
            int row = ch >> 2, c = ch & 3;
            int soff = row * GPAD + c * 8;
            size_t goffA = (size_t)(mb + row) * K + k0 + c * 8;
            size_t goffB = (size_t)(nb + row) * K + k0 + c * 8;
            cp16(base + soff,         Ahg + goffA);
            cp16(base + GTILE + soff, Bhg + goffB);
        }
        cp_commit();
    };

    load_stage(0, 0);

    for (int kb = 0; kb < NKB; ++kb) {
        cp_wait0();
        __syncthreads();
        if (kb + 1 < NKB) load_stage((kb + 1) & 1, (kb + 1) << 5);

        unsigned short* base = smg + (kb & 1) * GSTAGE;
        unsigned short* sAh = base;
        unsigned short* sBh = base + GTILE;

        #pragma unroll
        for (int kk = 0; kk < 2; ++kk) {
            uint32_t ah[4][4];
            #pragma unroll
            for (int mt = 0; mt < 4; ++mt) {
                int r = wm * 64 + mt * 16 + (lane & 15);
                int c = kk * 16 + (lane >> 4) * 8;
                ldsm4(ah[mt], sAh + r * GPAD + c);
            }
            uint32_t bh2[8][2];
            #pragma unroll
            for (int p = 0; p < 4; ++p) {
                int r = wn * 64 + p * 16 + ((lane >> 4) & 1) * 8 + (lane & 7);
                int c = kk * 16 + ((lane >> 3) & 1) * 8;
                uint32_t tmp[4];
                ldsm4(tmp, sBh + r * GPAD + c);
                bh2[2*p][0] = tmp[0]; bh2[2*p][1] = tmp[1];
                bh2[2*p+1][0] = tmp[2]; bh2[2*p+1][1] = tmp[3];
            }
            #pragma unroll
            for (int mt = 0; mt < 4; ++mt)
                #pragma unroll
                for (int nt = 0; nt < 8; ++nt)
                    mma_f16(acc[mt][nt], ah[mt], bh2[nt]);
        }
    }

    #pragma unroll
    for (int mt = 0; mt < 4; ++mt) {
        #pragma unroll
        for (int nt = 0; nt < 8; ++nt) {
            int r = mb + wm * 64 + mt * 16 + g;
            int c = nb + wn * 64 + nt * 8 + q * 2;
            float b0 = bias[c], b1 = bias[c + 1];
            float2 v0; v0.x = acc[mt][nt][0] + b0; v0.y = acc[mt][nt][1] + b1;
            float2 v1; v1.x = acc[mt][nt][2] + b0; v1.y = acc[mt][nt][3] + b1;
            *(float2*)(C + (size_t)r * N + c)       = v0;
            *(float2*)(C + (size_t)(r + 8) * N + c) = v1;
        }
    }
}

// ---------------------------------------------------------------------------
// 3) V transpose (fp16 in, fp16 out): Vt[bh][d][s].
// ---------------------------------------------------------------------------
__global__ void __launch_bounds__(256) v_transpose_kernel(
    const unsigned short* __restrict__ vseq, unsigned short* __restrict__ Vth)
{
    __shared__ unsigned short tile[64][66];
    int st = blockIdx.x, bh = blockIdx.y;
    int b = bh >> 4, h = bh & 15;
    int t = threadIdx.x;
    #pragma unroll
    for (int it = 0; it < 4; ++it) {
        int id = t + it * 256;            // 0..1023
        int sl = id >> 4, f4 = id & 15;
        size_t src = (size_t)(b * S_LEN + st * 64 + sl) * DMODEL + h * HDIM + f4 * 4;
        uint2 v = *(const uint2*)(vseq + src);
        *(uint32_t*)&tile[sl][f4 * 4]     = v.x;
        *(uint32_t*)&tile[sl][f4 * 4 + 2] = v.y;
    }
    __syncthreads();
    #pragma unroll
    for (int it = 0; it < 16; ++it) {
        int d  = it * 4 + (t >> 6);
        int sl = t & 63;
        size_t dst = ((size_t)bh * HDIM + d) * S_LEN + st * 64 + sl;
        Vth[dst] = tile[sl][d];
    }
}

// ---------------------------------------------------------------------------
// 4) fp16 flash attention, KV tile 128, f16x2 exp2, l-via-MMA ones rows,
//    pipelined S(t+1)-before-PV(t).
// ---------------------------------------------------------------------------
#define APAD 72            // K/Q row pad
#define VPAD 136           // V^T row pad
#define VROWS 80           // 64 d-rows + ones rows 64..71 + zero 72..79
#define AQT (128 * APAD)
#define KT  (128 * APAD)
#define VT  (VROWS * VPAD)
#define AST (KT + VT)
#define ATT_SMEM ((AQT + 2 * AST) * 2)

__global__ void __launch_bounds__(256) attn_mma_kernel(
    const unsigned short* __restrict__ Qh,
    const unsigned short* __restrict__ Kh, const unsigned short* __restrict__ Vth,
    unsigned short* __restrict__ Ch)
{
    extern __shared__ unsigned short sma[];
    unsigned short* sQh = sma;
    unsigned short* sKV = sma + AQT;

    int qt = gridDim.x - 1 - blockIdx.x;
    int bh = blockIdx.y;
    int b = bh >> 4, h = bh & 15;
    int t = threadIdx.x;
    int w = t >> 5, lane = t & 31;
    int g = lane >> 2, q = lane & 3;

    auto load_kv = [&](int st, int kt) {
        unsigned short* sg = sKV + st * AST;
        size_t kbase = ((size_t)bh * S_LEN + kt * 128) * HDIM;
        #pragma unroll
        for (int i = 0; i < 4; ++i) {
            int ch = t + i * 256;
            int row = ch >> 3, c = ch & 7;
            cp16(sg + row * APAD + c * 8, Kh + kbase + row * 64 + c * 8);
        }
        #pragma unroll
        for (int i = 0; i < 4; ++i) {
            int ch = t + i * 256;
            int row = ch >> 4, c = ch & 15;
            size_t vsrc = ((size_t)bh * HDIM + row) * S_LEN + kt * 128 + c * 8;
            cp16(sg + KT + row * VPAD + c * 8, Vth + vsrc);
        }
        cp_commit();
    };

    int nk = qt + 1;

    // prologue: Q, kv0, (kv1)
    size_t qbase = ((size_t)bh * S_LEN + qt * 128) * HDIM;
    #pragma unroll
    for (int i = 0; i < 4; ++i) {
        int ch = t + i * 256;
        int row = ch >> 3, c = ch & 7;
        cp16(sQh + row * APAD + c * 8, Qh + qbase + row * 64 + c * 8);
    }
    cp_commit();
    load_kv(0, 0);
    if (nk > 1) load_kv(1, 1);

    // init V^T rows 64..79 in both stages (cp.async never touches them)
    for (int idx = t; idx < 16 * VPAD; idx += 256) {
        int row = idx / VPAD, col = idx % VPAD;
        unsigned short val = (row < 8 && col < 128) ? (unsigned short)0x3C00
                                                    : (unsigned short)0;
        sKV[KT + (64 + row) * VPAD + col]       = val;
        sKV[AST + KT + (64 + row) * VPAD + col] = val;
    }

    if (nk > 1) cp_wait1(); else cp_wait0();
    __syncthreads();

    uint32_t qfh[4][4];
    #pragma unroll
    for (int kk = 0; kk < 4; ++kk) {
        int r = w * 16 + (lane & 15);
        int c = kk * 16 + (lane >> 4) * 8;
        ldsm4(qfh[kk], sQh + r * APAD + c);
    }

    float o[9][4];
    #pragma unroll
    for (int nt = 0; nt < 9; ++nt)
        #pragma unroll
        for (int e = 0; e < 4; ++e) o[nt][e] = 0.f;
    float mA = -1e30f, mB = -1e30f;

    int qrA = qt * 128 + w * 16 + g;
    float s_acc[16][4];
    uint32_t pA[16], pB[16];

    auto s_phase = [&](int st) {
        unsigned short* sK_ = sKV + st * AST;
        #pragma unroll
        for (int nt = 0; nt < 16; ++nt)
            #pragma unroll
            for (int e = 0; e < 4; ++e) s_acc[nt][e] = 0.f;
        #pragma unroll
        for (int kk = 0; kk < 4; ++kk) {
            uint32_t bh2[16][2];
            #pragma unroll
            for (int p = 0; p < 8; ++p) {
                int r = p * 16 + ((lane >> 4) & 1) * 8 + (lane & 7);
                int c = kk * 16 + ((lane >> 3) & 1) * 8;
                uint32_t tmp[4];
                ldsm4(tmp, sK_ + r * APAD + c);
                bh2[2*p][0] = tmp[0]; bh2[2*p][1] = tmp[1];
                bh2[2*p+1][0] = tmp[2]; bh2[2*p+1][1] = tmp[3];
            }
            #pragma unroll
            for (int nt = 0; nt < 16; ++nt)
                mma_f16(s_acc[nt], qfh[kk], bh2[nt]);
        }
    };

    auto pv_phase = [&](int st) {
        unsigned short* sV_ = sKV + st * AST + KT;
        #pragma unroll
        for (int kk = 0; kk < 8; ++kk) {
            int n0 = 2 * kk, n1 = 2 * kk + 1;
            uint32_t ph[4];
            ph[0] = pA[n0]; ph[1] = pB[n0];
            ph[2] = pA[n1]; ph[3] = pB[n1];
            uint32_t vh2[10][2];
            #pragma unroll
            for (int p = 0; p < 5; ++p) {
                int r = p * 16 + ((lane >> 4) & 1) * 8 + (lane & 7);
                int c = kk * 16 + ((lane >> 3) & 1) * 8;
                uint32_t tmp[4];
                ldsm4(tmp, sV_ + r * VPAD + c);
                vh2[2*p][0] = tmp[0]; vh2[2*p][1] = tmp[1];
                vh2[2*p+1][0] = tmp[2]; vh2[2*p+1][1] = tmp[3];
            }
            #pragma unroll
            for (int nt = 0; nt < 9; ++nt)
                mma_f16(o[nt], ph, vh2[nt]);
        }
    };

    s_phase(0);

    for (int kt = 0; kt < nk; ++kt) {
        // ---- softmax on tile kt ----
        int kb0 = kt * 128;
        if (kb0 + 127 > qrA) {
            #pragma unroll
            for (int nt = 0; nt < 16; ++nt) {
                int colb = kb0 + nt * 8 + 2 * q;
                if (colb     > qrA)     s_acc[nt][0] = -1e30f;
                if (colb + 1 > qrA)     s_acc[nt][1] = -1e30f;
                if (colb     > qrA + 8) s_acc[nt][2] = -1e30f;
                if (colb + 1 > qrA + 8) s_acc[nt][3] = -1e30f;
            }
        }
        float mxA = -1e30f, mxB = -1e30f;
        #pragma unroll
        for (int nt = 0; nt < 16; ++nt) {
            mxA = fmaxf(mxA, fmaxf(s_acc[nt][0], s_acc[nt][1]));
            mxB = fmaxf(mxB, fmaxf(s_acc[nt][2], s_acc[nt][3]));
        }
        mxA = fmaxf(mxA, __shfl_xor_sync(0xffffffffu, mxA, 1));
        mxA = fmaxf(mxA, __shfl_xor_sync(0xffffffffu, mxA, 2));
        mxB = fmaxf(mxB, __shfl_xor_sync(0xffffffffu, mxB, 1));
        mxB = fmaxf(mxB, __shfl_xor_sync(0xffffffffu, mxB, 2));
        float mnA = fmaxf(mA, mxA), mnB = fmaxf(mB, mxB);
        float corrA = exp2f(mA - mnA), corrB = exp2f(mB - mnB);
        mA = mnA;  mB = mnB;
        #pragma unroll
        for (int nt = 0; nt < 16; ++nt) {
            pA[nt] = ex2_h2(f2h2(s_acc[nt][0] - mnA, s_acc[nt][1] - mnA));
            pB[nt] = ex2_h2(f2h2(s_acc[nt][2] - mnB, s_acc[nt][3] - mnB));
        }
        #pragma unroll
        for (int nt = 0; nt < 9; ++nt) {
            o[nt][0] *= corrA; o[nt][1] *= corrA;
            o[nt][2] *= corrB; o[nt][3] *= corrB;
        }

        // ---- S(kt+1) before PV(kt) ----
        if (kt + 1 < nk) {
            cp_wait0();
            __syncthreads();
            s_phase((kt + 1) & 1);
        }

        pv_phase(kt & 1);

        __syncthreads();
        if (kt + 2 < nk) load_kv(kt & 1, kt + 2);
    }

    float invA = 1.f / o[8][0], invB = 1.f / o[8][2];
    int rowA = qt * 128 + w * 16 + g;
    size_t baseA = ((size_t)(b * S_LEN + rowA)) * DMODEL + h * HDIM;
    size_t baseB = baseA + (size_t)8 * DMODEL;
    #pragma unroll
    for (int nt = 0; nt < 8; ++nt) {
        int c = nt * 8 + 2 * q;
        float a0 = o[nt][0] * invA, a1 = o[nt][1] * invA;
        float b0 = o[nt][2] * invB, b1 = o[nt][3] * invB;
        *(uint32_t*)(Ch + baseA + c) = f2h2(a0, a1);
        *(uint32_t*)(Ch + baseB + c) = f2h2(b0, b1);
    }
}

// ---------------------------------------------------------------------------
// Launcher
// ---------------------------------------------------------------------------
extern "C" void kernel_launch(void* const* d_in, const int* in_sizes, int n_in,
                              void* d_out, int out_size)
{
    const float* hs     = (const float*)d_in[0];
    const float* gamma  = (const float*)d_in[1];
    const float* beta   = (const float*)d_in[2];
    const float* qkv_w  = (const float*)d_in[3];
    const float* qkv_b  = (const float*)d_in[4];
    const float* proj_w = (const float*)d_in[5];
    const float* proj_b = (const float*)d_in[6];
    float* out = (float*)d_out;

    void *pxh, *pwqh, *pwph, *pch, *pqh, *pkh, *pvs, *pvh;
    cudaGetSymbolAddress(&pxh,  g_xh);
    cudaGetSymbolAddress(&pwqh, g_wqh); cudaGetSymbolAddress(&pwph, g_wph);
    cudaGetSymbolAddress(&pch,  g_ch);
    cudaGetSymbolAddress(&pqh,  g_qhh); cudaGetSymbolAddress(&pkh,  g_khh);
    cudaGetSymbolAddress(&pvs,  g_vseq); cudaGetSymbolAddress(&pvh,  g_vth);

    cudaFuncSetAttribute(qkv_gemm_rope,
        cudaFuncAttributeMaxDynamicSharedMemorySize, GEMM_SMEM);
    cudaFuncSetAttribute(mma_gemm_smem,
        cudaFuncAttributeMaxDynamicSharedMemorySize, GEMM_SMEM);
    cudaFuncSetAttribute(attn_mma_kernel,
        cudaFuncAttributeMaxDynamicSharedMemorySize, ATT_SMEM);

    // 1) LayerNorm -> fp16
    ln_split_kernel<<<ROWS, 256>>>(hs, gamma, beta, (unsigned short*)pxh);

    // weight conversions
    w_f16_kernel<<<(QKVD*DMODEL/4)/256, 256>>>(qkv_w,
        (unsigned short*)pwqh, QKVD*DMODEL/4);
    w_f16_kernel<<<(DMODEL*DMODEL/4)/256, 256>>>(proj_w,
        (unsigned short*)pwph, DMODEL*DMODEL/4);

    // 2) QKV GEMM with fused bias+rope+relayout (fp16 out)
    qkv_gemm_rope<<<dim3(QKVD/128, ROWS/128), 128, GEMM_SMEM>>>(
        (unsigned short*)pxh, (unsigned short*)pwqh, qkv_b,
        (unsigned short*)pqh, (unsigned short*)pkh, (unsigned short*)pvs);

    // 3) V transpose (fp16 -> fp16)
    v_transpose_kernel<<<dim3(S_LEN/64, BH), 256>>>(
        (unsigned short*)pvs, (unsigned short*)pvh);

    // 4) Attention (pipelined S/PV overlap)
    attn_mma_kernel<<<dim3(S_LEN/128, BH), 256, ATT_SMEM>>>(
        (unsigned short*)pqh, (unsigned short*)pkh, (unsigned short*)pvh,
        (unsigned short*)pch);

    // 5) Output projection (fp32 out)
    mma_gemm_smem<<<dim3(DMODEL/128, ROWS/128), 128, GEMM_SMEM>>>(
        (unsigned short*)pch, (unsigned short*)pwph,
        proj_b, out, ROWS, DMODEL, DMODEL);
}